// round 15
// baseline (speedup 1.0000x reference)
#include <cuda_runtime.h>
#include <cuda_fp16.h>
#include <mma.h>
#include <cstdint>

using namespace nvcuda;

#define N_NODES 10000
#define N_PAD   10240          // 20 * 512
#define GY      20             // row groups in GEMM grid
#define N_EDGES 65536
#define CIN1    16
#define HID     64

// ---- static device scratch (no allocations allowed) ----
__device__ __half g_Gh[(size_t)N_PAD * 4096];      // per-node factor, fp16 (84 MB)
__device__ __half g_Xh[N_PAD * 64];                // fp16 split of node features
__device__ __half g_Xl[N_PAD * 64];
__device__ __half g_Bh[64 * 4096];                 // fp16 split of permuted W2
__device__ __half g_Bl[64 * 4096];
__device__ float  g_h[(size_t)N_EDGES * 64];       // edge-MLP hidden (fp32)
__device__ float  g_XB[N_NODES * 64];              // bias-path per node
__device__ float  g_agg[N_NODES * 64];             // scatter accumulator
__device__ float  g_y[N_NODES * 64];               // layer-1 output
__device__ float  g_z[N_NODES * 64];               // layer-2 output
__device__ float  g_deg[N_NODES];                  // in-degree (by dst)

// ---- edge sort-by-src scratch ----
__device__ int g_cnt[N_NODES];
__device__ int g_off[N_NODES];
__device__ int g_cur[N_NODES];
__device__ int g_se[N_EDGES];                      // sorted edge id
__device__ int g_ss[N_EDGES];                      // sorted src
__device__ int g_sd[N_EDGES];                      // sorted dst

// ---------------------------------------------------------------------------
__global__ void k_init() {
    int i = blockIdx.x * blockDim.x + threadIdx.x;
    if (i < N_NODES * 64) g_agg[i] = 0.f;
    if (i < N_NODES) { g_deg[i] = 0.f; g_cnt[i] = 0; g_cur[i] = 0; }
}

__global__ void k_zero_agg() {
    int i = blockIdx.x * blockDim.x + threadIdx.x;
    if (i < N_NODES * 64) g_agg[i] = 0.f;
}

__global__ void k_hist(const int* __restrict__ ei) {
    int e = blockIdx.x * blockDim.x + threadIdx.x;
    if (e >= N_EDGES) return;
    atomicAdd(&g_cnt[ei[e]], 1);
    atomicAdd(&g_deg[ei[N_EDGES + e]], 1.f);
}

__global__ void k_scan() {
    __shared__ int s[1024];
    __shared__ int carry;
    int tid = threadIdx.x;
    if (tid == 0) carry = 0;
    __syncthreads();
    for (int base = 0; base < N_NODES; base += 1024) {
        int i = base + tid;
        int v = (i < N_NODES) ? g_cnt[i] : 0;
        s[tid] = v;
        __syncthreads();
        for (int d = 1; d < 1024; d <<= 1) {
            int t = (tid >= d) ? s[tid - d] : 0;
            __syncthreads();
            s[tid] += t;
            __syncthreads();
        }
        if (i < N_NODES) g_off[i] = s[tid] - v + carry;
        __syncthreads();
        if (tid == 0) carry += s[1023];
        __syncthreads();
    }
}

__global__ void k_scatter(const int* __restrict__ ei) {
    int e = blockIdx.x * blockDim.x + threadIdx.x;
    if (e >= N_EDGES) return;
    int src = ei[e];
    int pos = g_off[src] + atomicAdd(&g_cur[src], 1);
    g_se[pos] = e;
    g_ss[pos] = src;
    g_sd[pos] = ei[N_EDGES + e];
}

// ---- fp16 split conversions ------------------------------------------------
template <int CIN>
__global__ void k_conv_X(const float* __restrict__ X) {
    int idx = blockIdx.x * blockDim.x + threadIdx.x;
    if (idx >= N_PAD * CIN) return;
    int n = idx / CIN;
    float v = (n < N_NODES) ? X[idx] : 0.f;
    __half h = __float2half(v);
    g_Xh[idx] = h;
    g_Xl[idx] = __float2half(v - __half2float(h));
}

// W2 [64, CIN*64] -> B [CIN, 4096] permuted: B[i, m*64+o] = W2[m, i*64+o]
template <int CIN>
__global__ void k_conv_B(const float* __restrict__ W2) {
    int idx = blockIdx.x * blockDim.x + threadIdx.x;
    if (idx >= CIN * 4096) return;
    int i = idx >> 12;
    int c = idx & 4095;
    int m = c >> 6, o = c & 63;
    float v = W2[(size_t)m * (CIN * 64) + i * 64 + o];
    __half h = __float2half(v);
    g_Bh[idx] = h;
    g_Bl[idx] = __float2half(v - __half2float(h));
}

// h[e,j] = relu(b1[j] + sum_k ea[e,k]*w1[k,j])  (fp32)
__global__ void k_edge_hidden(const float* __restrict__ ea,
                              const float* __restrict__ w1,
                              const float* __restrict__ b1) {
    int idx = blockIdx.x * blockDim.x + threadIdx.x;
    if (idx >= N_EDGES * 64) return;
    int e = idx >> 6, j = idx & 63;
    const float* a = ea + (size_t)e * 4;
    float v = b1[j];
#pragma unroll
    for (int k = 0; k < 4; ++k) v = fmaf(a[k], w1[k * 64 + j], v);
    g_h[idx] = fmaxf(v, 0.f);
}

// ---- G = X @ B via HMMA ----------------------------------------------------
// grid (64 col-blocks, GY row-groups), block 256 (8 warps).
// Persistent B slab in smem.  For K=64 also stage the 128-row A tile in smem
// per iteration (coalesced -> LDSM frag loads).  Epilogue: fp32 C slab ->
// packed uint4 half stores (4 coalesced STG.128 per lane).
template <int K>
__global__ void __launch_bounds__(256) k_gemm_wmma6() {
    extern __shared__ __align__(16) unsigned char smem_raw[];
    constexpr int AELE = (K > 16) ? 128 * K : 0;
    __half* Bsh = (__half*)smem_raw;
    __half* Bsl = Bsh + K * 64;
    __half* Ash = Bsl + K * 64;
    __half* Asl = Ash + AELE;
    float*  Cs  = (float*)(Asl + AELE);     // 8 warps * 16*72 fp32

    const int tid  = threadIdx.x;
    const int col0 = blockIdx.x * 64;
    const int row_start = blockIdx.y * (N_PAD / GY);

    for (int i = tid; i < K * 8; i += 256) {
        int k = i >> 3, p = i & 7;
        ((uint4*)Bsh)[i] = *(const uint4*)(g_Bh + (size_t)k * 4096 + col0 + p * 8);
        ((uint4*)Bsl)[i] = *(const uint4*)(g_Bl + (size_t)k * 4096 + col0 + p * 8);
    }
    __syncthreads();

    const int w    = tid >> 5;
    const int lane = tid & 31;
    float* cw = Cs + w * (16 * 72);

    for (int r0 = row_start; r0 < row_start + (N_PAD / GY); r0 += 128) {
        if (K > 16) {
            __syncthreads();   // prior iteration's A reads complete
            for (int i = tid; i < (128 * K) / 8; i += 256) {
                ((uint4*)Ash)[i] = ((const uint4*)(g_Xh + (size_t)r0 * K))[i];
                ((uint4*)Asl)[i] = ((const uint4*)(g_Xl + (size_t)r0 * K))[i];
            }
            __syncthreads();
        }
        const int rw = r0 + w * 16;

        wmma::fragment<wmma::accumulator, 16, 16, 16, float> acc[4];
#pragma unroll
        for (int t = 0; t < 4; ++t) wmma::fill_fragment(acc[t], 0.f);

#pragma unroll
        for (int kc = 0; kc < K; kc += 16) {
            wmma::fragment<wmma::matrix_a, 16, 16, 16, __half, wmma::row_major> ah, al;
            if (K > 16) {
                wmma::load_matrix_sync(ah, Ash + (w * 16) * K + kc, K);
                wmma::load_matrix_sync(al, Asl + (w * 16) * K + kc, K);
            } else {
                wmma::load_matrix_sync(ah, g_Xh + (size_t)rw * K + kc, K);
                wmma::load_matrix_sync(al, g_Xl + (size_t)rw * K + kc, K);
            }
#pragma unroll
            for (int t = 0; t < 4; ++t) {
                wmma::fragment<wmma::matrix_b, 16, 16, 16, __half, wmma::row_major> bh, bl;
                wmma::load_matrix_sync(bh, Bsh + kc * 64 + t * 16, 64);
                wmma::load_matrix_sync(bl, Bsl + kc * 64 + t * 16, 64);
                wmma::mma_sync(acc[t], ah, bh, acc[t]);
                wmma::mma_sync(acc[t], ah, bl, acc[t]);
                wmma::mma_sync(acc[t], al, bh, acc[t]);
            }
        }
        // epilogue: frags -> fp32 slab -> packed half stores (coalesced 128B)
#pragma unroll
        for (int t = 0; t < 4; ++t)
            wmma::store_matrix_sync(cw + t * 16, acc[t], 72, wmma::mem_row_major);
        __syncwarp();
#pragma unroll
        for (int q = 0; q < 4; ++q) {
            int idx = lane + q * 32;          // 0..127
            int row = idx >> 3, part = idx & 7;
            float4 a = *(const float4*)&cw[row * 72 + part * 8];
            float4 b = *(const float4*)&cw[row * 72 + part * 8 + 4];
            __half2 h0 = __floats2half2_rn(a.x, a.y);
            __half2 h1 = __floats2half2_rn(a.z, a.w);
            __half2 h2 = __floats2half2_rn(b.x, b.y);
            __half2 h3 = __floats2half2_rn(b.z, b.w);
            uint4 v;
            v.x = *(unsigned*)&h0; v.y = *(unsigned*)&h1;
            v.z = *(unsigned*)&h2; v.w = *(unsigned*)&h3;
            *(uint4*)(g_Gh + (size_t)(rw + row) * 4096 + col0 + part * 8) = v;
        }
        __syncwarp();
    }
}

// XB[n,o] = sum_i X[n,i] * b2[i*64 + o]
template <int CIN>
__global__ void k_xb(const float* __restrict__ X, const float* __restrict__ b2) {
    int idx = blockIdx.x * blockDim.x + threadIdx.x;
    if (idx >= N_NODES * 64) return;
    int n = idx >> 6, o = idx & 63;
    const float* xr = X + (size_t)n * CIN;
    float v = 0.f;
#pragma unroll
    for (int i = 0; i < CIN; ++i) v = fmaf(xr[i], b2[i * 64 + o], v);
    g_XB[idx] = v;
}

// one warp per SORTED edge.  Lane l: rows it*4 + l/8, cols (l%8)*8..+7 via one
// LDG.128; shfl_xor(8,16) column reduction; XB folded at the atomic.  (R13)
__global__ void k_edge_msg() {
    int p    = (blockIdx.x * blockDim.x + threadIdx.x) >> 5;
    int lane = threadIdx.x & 31;
    if (p >= N_EDGES) return;
    const int e   = g_se[p];
    const int src = g_ss[p];
    const int dst = g_sd[p];

    const float h0 = g_h[(size_t)e * 64 + lane];
    const float h1 = g_h[(size_t)e * 64 + 32 + lane];
    const __half* g = g_Gh + (size_t)src * 4096;

    const int rsub = lane >> 3;
    const int cblk = (lane & 7) * 8;

    float acc[8];
#pragma unroll
    for (int j = 0; j < 8; ++j) acc[j] = 0.f;

    const unsigned FULL = 0xffffffffu;
#pragma unroll
    for (int it = 0; it < 16; ++it) {
        const int r = it * 4 + rsub;
        float hr = (it < 8) ? __shfl_sync(FULL, h0, r)
                            : __shfl_sync(FULL, h1, r - 32);
        uint4 gv = *(const uint4*)(g + r * 64 + cblk);
        const __half2* gh = (const __half2*)&gv;
#pragma unroll
        for (int j = 0; j < 4; ++j) {
            float2 f = __half22float2(gh[j]);
            acc[2 * j]     = fmaf(hr, f.x, acc[2 * j]);
            acc[2 * j + 1] = fmaf(hr, f.y, acc[2 * j + 1]);
        }
    }
#pragma unroll
    for (int j = 0; j < 8; ++j) {
        acc[j] += __shfl_xor_sync(FULL, acc[j], 8);
        acc[j] += __shfl_xor_sync(FULL, acc[j], 16);
    }
    const int j0 = rsub * 2;
    const int c0 = cblk + j0;
    float2 xb = *(const float2*)&g_XB[src * 64 + c0];
    atomicAdd(&g_agg[dst * 64 + c0],     acc[j0]     + xb.x);
    atomicAdd(&g_agg[dst * 64 + c0 + 1], acc[j0 + 1] + xb.y);
}

// out[n,o] = relu(agg/max(deg,1) + x@root + bias)
template <int CIN>
__global__ void k_finalize(const float* __restrict__ Xin,
                           const float* __restrict__ root,
                           const float* __restrict__ bias,
                           float* __restrict__ out) {
    int idx = blockIdx.x * blockDim.x + threadIdx.x;
    if (idx >= N_NODES * 64) return;
    int n = idx >> 6, o = idx & 63;
    float inv = 1.f / fmaxf(g_deg[n], 1.f);
    float v = g_agg[idx] * inv + bias[o];
    const float* xr = Xin + (size_t)n * CIN;
#pragma unroll 8
    for (int i = 0; i < CIN; ++i) v = fmaf(xr[i], root[i * 64 + o], v);
    out[idx] = fmaxf(v, 0.f);
}

// readout: warp per node
__global__ void k_readout(const float* __restrict__ w1, const float* __restrict__ b1,
                          const float* __restrict__ w2, const float* __restrict__ b2,
                          float* __restrict__ out) {
    int warp = (blockIdx.x * blockDim.x + threadIdx.x) >> 5;
    int lane = threadIdx.x & 31;
    if (warp >= N_NODES) return;
    const float* zr = g_z + (size_t)warp * 64;
    float z0 = zr[lane], z1 = zr[lane + 32];
    float p[8];
#pragma unroll
    for (int j = 0; j < 8; ++j)
        p[j] = z0 * w1[lane * 8 + j] + z1 * w1[(lane + 32) * 8 + j];
    const unsigned FULL = 0xffffffffu;
#pragma unroll
    for (int off = 16; off; off >>= 1)
#pragma unroll
        for (int j = 0; j < 8; ++j) p[j] += __shfl_down_sync(FULL, p[j], off);
    if (lane == 0) {
        float r = b2[0];
#pragma unroll
        for (int j = 0; j < 8; ++j) r += fmaxf(p[j] + b1[j], 0.f) * w2[j];
        out[warp] = r;
    }
}

// ---------------------------------------------------------------------------
extern "C" void kernel_launch(void* const* d_in, const int* in_sizes, int n_in,
                              void* d_out, int out_size) {
    const float* x      = (const float*)d_in[0];
    const int*   ei     = (const int*)d_in[1];     // int32 (jax x64 disabled)
    const float* ea     = (const float*)d_in[2];
    const float* nn1_w1 = (const float*)d_in[3];
    const float* nn1_b1 = (const float*)d_in[4];
    const float* nn1_w2 = (const float*)d_in[5];
    const float* nn1_b2 = (const float*)d_in[6];
    const float* root1  = (const float*)d_in[7];
    const float* bias1  = (const float*)d_in[8];
    const float* nn2_w1 = (const float*)d_in[9];
    const float* nn2_b1 = (const float*)d_in[10];
    const float* nn2_w2 = (const float*)d_in[11];
    const float* nn2_b2 = (const float*)d_in[12];
    const float* root2  = (const float*)d_in[13];
    const float* bias2  = (const float*)d_in[14];
    const float* lin1_w = (const float*)d_in[15];
    const float* lin1_b = (const float*)d_in[16];
    const float* lin2_w = (const float*)d_in[17];
    const float* lin2_b = (const float*)d_in[18];
    float* out = (float*)d_out;

    float* d_y = nullptr; float* d_z = nullptr;
    cudaGetSymbolAddress((void**)&d_y, g_y);
    cudaGetSymbolAddress((void**)&d_z, g_z);

    const int SMEM1 = 2 * CIN1 * 64 * 2 + 8 * 16 * 72 * 4;                    // 40960
    const int SMEM2 = 2 * HID * 64 * 2 + 2 * 128 * HID * 2 + 8 * 16 * 72 * 4; // 86016
    cudaFuncSetAttribute(k_gemm_wmma6<CIN1>,
                         cudaFuncAttributeMaxDynamicSharedMemorySize, SMEM1);
    cudaFuncSetAttribute(k_gemm_wmma6<HID>,
                         cudaFuncAttributeMaxDynamicSharedMemorySize, SMEM2);

    const int T = 256;
    const int bNO  = (N_NODES * 64 + T - 1) / T;
    const int bE   = (N_EDGES + T - 1) / T;
    const int bEH  = (N_EDGES * 64 + T - 1) / T;
    const int bMSG = (N_EDGES * 32 + T - 1) / T;   // warp per edge
    const int bRD  = (N_NODES * 32 + T - 1) / T;
    dim3 gW(64, GY);

    // launch index 3 is profiled — keep the NEW gemm<16> there.
    k_conv_B<CIN1><<<(CIN1 * 4096 + T - 1) / T, T>>>(nn1_w2);      // 0
    k_conv_X<CIN1><<<(N_PAD * CIN1 + T - 1) / T, T>>>(x);          // 1
    k_init<<<bNO, T>>>();                                          // 2
    k_gemm_wmma6<CIN1><<<gW, 256, SMEM1>>>();                      // 3 <- profiled
    k_hist<<<bE, T>>>(ei);                                         // 4
    k_scan<<<1, 1024>>>();                                         // 5
    k_scatter<<<bE, T>>>(ei);                                      // 6
    k_edge_hidden<<<bEH, T>>>(ea, nn1_w1, nn1_b1);                 // 7
    k_xb<CIN1><<<bNO, T>>>(x, nn1_b2);                             // 8
    k_edge_msg<<<bMSG, T>>>();                                     // 9
    k_finalize<CIN1><<<bNO, T>>>(x, root1, bias1, d_y);            // 10

    // ---- layer 2 (cin = 64) ----
    k_zero_agg<<<bNO, T>>>();
    k_conv_B<HID><<<(HID * 4096 + T - 1) / T, T>>>(nn2_w2);
    k_conv_X<HID><<<(N_PAD * HID + T - 1) / T, T>>>(d_y);
    k_edge_hidden<<<bEH, T>>>(ea, nn2_w1, nn2_b1);
    k_gemm_wmma6<HID><<<gW, 256, SMEM2>>>();
    k_xb<HID><<<bNO, T>>>(d_y, nn2_b2);
    k_edge_msg<<<bMSG, T>>>();
    k_finalize<HID><<<bNO, T>>>(d_y, root2, bias2, d_z);

    // ---- readout ----
    k_readout<<<bRD, T>>>(lin1_w, lin1_b, lin2_w, lin2_b, out);
}

// round 17
// speedup vs baseline: 1.3955x; 1.3955x over previous
#include <cuda_runtime.h>
#include <cuda_fp16.h>
#include <mma.h>
#include <cstdint>

using namespace nvcuda;

#define N_NODES 10000
#define N_PAD   10240          // 20 * 512
#define GY      20             // row groups in GEMM grid
#define N_EDGES 65536
#define CIN1    16
#define HID     64

// ---- static device scratch (no allocations allowed) ----
__device__ __half g_Gh[(size_t)N_PAD * 4096];      // per-node factor, fp16 (84 MB)
__device__ __half g_Xh[N_PAD * 64];                // fp16 node features
__device__ __half g_Bh[64 * 4096];                 // fp16 permuted W2
__device__ float  g_h[(size_t)N_EDGES * 64];       // edge-MLP hidden (fp32)
__device__ float  g_XB[N_NODES * 64];              // bias-path per node
__device__ float  g_agg[N_NODES * 64];             // scatter accumulator
__device__ float  g_y[N_NODES * 64];               // layer-1 output
__device__ float  g_z[N_NODES * 64];               // layer-2 output
__device__ float  g_deg[N_NODES];                  // in-degree (by dst)

// ---- edge sort-by-src scratch ----
__device__ int g_cnt[N_NODES];
__device__ int g_off[N_NODES];
__device__ int g_cur[N_NODES];
__device__ int g_se[N_EDGES];                      // sorted edge id
__device__ int g_ss[N_EDGES];                      // sorted src
__device__ int g_sd[N_EDGES];                      // sorted dst

// ---------------------------------------------------------------------------
__global__ void k_init() {
    int i = blockIdx.x * blockDim.x + threadIdx.x;
    if (i < N_NODES * 64) g_agg[i] = 0.f;
    if (i < N_NODES) { g_deg[i] = 0.f; g_cnt[i] = 0; g_cur[i] = 0; }
}

__global__ void k_zero_agg() {
    int i = blockIdx.x * blockDim.x + threadIdx.x;
    if (i < N_NODES * 64) g_agg[i] = 0.f;
}

__global__ void k_hist(const int* __restrict__ ei) {
    int e = blockIdx.x * blockDim.x + threadIdx.x;
    if (e >= N_EDGES) return;
    atomicAdd(&g_cnt[ei[e]], 1);
    atomicAdd(&g_deg[ei[N_EDGES + e]], 1.f);
}

__global__ void k_scan() {
    __shared__ int s[1024];
    __shared__ int carry;
    int tid = threadIdx.x;
    if (tid == 0) carry = 0;
    __syncthreads();
    for (int base = 0; base < N_NODES; base += 1024) {
        int i = base + tid;
        int v = (i < N_NODES) ? g_cnt[i] : 0;
        s[tid] = v;
        __syncthreads();
        for (int d = 1; d < 1024; d <<= 1) {
            int t = (tid >= d) ? s[tid - d] : 0;
            __syncthreads();
            s[tid] += t;
            __syncthreads();
        }
        if (i < N_NODES) g_off[i] = s[tid] - v + carry;
        __syncthreads();
        if (tid == 0) carry += s[1023];
        __syncthreads();
    }
}

__global__ void k_scatter(const int* __restrict__ ei) {
    int e = blockIdx.x * blockDim.x + threadIdx.x;
    if (e >= N_EDGES) return;
    int src = ei[e];
    int pos = g_off[src] + atomicAdd(&g_cur[src], 1);
    g_se[pos] = e;
    g_ss[pos] = src;
    g_sd[pos] = ei[N_EDGES + e];
}

// ---- fp16 conversions (single-term; quantization error ~2^-11, measured
// safe: one such source -> 6.6e-5 final rel_err) ----------------------------
template <int CIN>
__global__ void k_conv_X(const float* __restrict__ X) {
    int idx = blockIdx.x * blockDim.x + threadIdx.x;
    if (idx >= N_PAD * CIN) return;
    int n = idx / CIN;
    float v = (n < N_NODES) ? X[idx] : 0.f;
    g_Xh[idx] = __float2half(v);
}

// W2 [64, CIN*64] -> B [CIN, 4096] permuted: B[i, m*64+o] = W2[m, i*64+o]
template <int CIN>
__global__ void k_conv_B(const float* __restrict__ W2) {
    int idx = blockIdx.x * blockDim.x + threadIdx.x;
    if (idx >= CIN * 4096) return;
    int i = idx >> 12;
    int c = idx & 4095;
    int m = c >> 6, o = c & 63;
    g_Bh[idx] = __float2half(W2[(size_t)m * (CIN * 64) + i * 64 + o]);
}

// h[e,j] = relu(b1[j] + sum_k ea[e,k]*w1[k,j])  (fp32)
__global__ void k_edge_hidden(const float* __restrict__ ea,
                              const float* __restrict__ w1,
                              const float* __restrict__ b1) {
    int idx = blockIdx.x * blockDim.x + threadIdx.x;
    if (idx >= N_EDGES * 64) return;
    int e = idx >> 6, j = idx & 63;
    const float* a = ea + (size_t)e * 4;
    float v = b1[j];
#pragma unroll
    for (int k = 0; k < 4; ++k) v = fmaf(a[k], w1[k * 64 + j], v);
    g_h[idx] = fmaxf(v, 0.f);
}

// ---- G = X @ B via HMMA, single-term fp16, persistent-B, smem epilogue ----
// grid (64 col-blocks, GY row-groups), block 256 (8 warps).  (wmma4 structure)
template <int K>
__global__ void __launch_bounds__(256) k_gemm_wmma7() {
    extern __shared__ __align__(16) unsigned char smem_raw[];
    __half* Bsh = (__half*)smem_raw;
    float*  Cs  = (float*)(Bsh + K * 64);     // 8 warps * 16*72 fp32

    const int tid  = threadIdx.x;
    const int col0 = blockIdx.x * 64;
    const int row_start = blockIdx.y * (N_PAD / GY);

    for (int i = tid; i < K * 8; i += 256) {
        int k = i >> 3, p = i & 7;
        ((uint4*)Bsh)[i] = *(const uint4*)(g_Bh + (size_t)k * 4096 + col0 + p * 8);
    }
    __syncthreads();

    const int w    = tid >> 5;
    const int lane = tid & 31;
    float* cw = Cs + w * (16 * 72);

    for (int r = row_start + w * 16; r < row_start + (N_PAD / GY); r += 128) {
        wmma::fragment<wmma::accumulator, 16, 16, 16, float> acc[4];
#pragma unroll
        for (int t = 0; t < 4; ++t) wmma::fill_fragment(acc[t], 0.f);

#pragma unroll
        for (int kc = 0; kc < K; kc += 16) {
            wmma::fragment<wmma::matrix_a, 16, 16, 16, __half, wmma::row_major> ah;
            wmma::load_matrix_sync(ah, g_Xh + (size_t)r * K + kc, K);
#pragma unroll
            for (int t = 0; t < 4; ++t) {
                wmma::fragment<wmma::matrix_b, 16, 16, 16, __half, wmma::row_major> bh;
                wmma::load_matrix_sync(bh, Bsh + kc * 64 + t * 16, 64);
                wmma::mma_sync(acc[t], ah, bh, acc[t]);
            }
        }
#pragma unroll
        for (int t = 0; t < 4; ++t)
            wmma::store_matrix_sync(cw + t * 16, acc[t], 72, wmma::mem_row_major);
        __syncwarp();
#pragma unroll
        for (int rr = 0; rr < 16; ++rr) {
            float2 v = *(const float2*)&cw[rr * 72 + 2 * lane];
            ((__half2*)(g_Gh + (size_t)(r + rr) * 4096 + col0))[lane] =
                __floats2half2_rn(v.x, v.y);
        }
        __syncwarp();
    }
}

// XB[n,o] = sum_i X[n,i] * b2[i*64 + o]
template <int CIN>
__global__ void k_xb(const float* __restrict__ X, const float* __restrict__ b2) {
    int idx = blockIdx.x * blockDim.x + threadIdx.x;
    if (idx >= N_NODES * 64) return;
    int n = idx >> 6, o = idx & 63;
    const float* xr = X + (size_t)n * CIN;
    float v = 0.f;
#pragma unroll
    for (int i = 0; i < CIN; ++i) v = fmaf(xr[i], b2[i * 64 + o], v);
    g_XB[idx] = v;
}

// one warp per SORTED edge.  Lane l: rows it*4 + l/8, cols (l%8)*8..+7 via one
// LDG.128; shfl_xor(8,16) column reduction; XB folded at the atomic.  (R13)
__global__ void k_edge_msg() {
    int p    = (blockIdx.x * blockDim.x + threadIdx.x) >> 5;
    int lane = threadIdx.x & 31;
    if (p >= N_EDGES) return;
    const int e   = g_se[p];
    const int src = g_ss[p];
    const int dst = g_sd[p];

    const float h0 = g_h[(size_t)e * 64 + lane];
    const float h1 = g_h[(size_t)e * 64 + 32 + lane];
    const __half* g = g_Gh + (size_t)src * 4096;

    const int rsub = lane >> 3;
    const int cblk = (lane & 7) * 8;

    float acc[8];
#pragma unroll
    for (int j = 0; j < 8; ++j) acc[j] = 0.f;

    const unsigned FULL = 0xffffffffu;
#pragma unroll
    for (int it = 0; it < 16; ++it) {
        const int r = it * 4 + rsub;
        float hr = (it < 8) ? __shfl_sync(FULL, h0, r)
                            : __shfl_sync(FULL, h1, r - 32);
        uint4 gv = *(const uint4*)(g + r * 64 + cblk);
        const __half2* gh = (const __half2*)&gv;
#pragma unroll
        for (int j = 0; j < 4; ++j) {
            float2 f = __half22float2(gh[j]);
            acc[2 * j]     = fmaf(hr, f.x, acc[2 * j]);
            acc[2 * j + 1] = fmaf(hr, f.y, acc[2 * j + 1]);
        }
    }
#pragma unroll
    for (int j = 0; j < 8; ++j) {
        acc[j] += __shfl_xor_sync(FULL, acc[j], 8);
        acc[j] += __shfl_xor_sync(FULL, acc[j], 16);
    }
    const int j0 = rsub * 2;
    const int c0 = cblk + j0;
    float2 xb = *(const float2*)&g_XB[src * 64 + c0];
    atomicAdd(&g_agg[dst * 64 + c0],     acc[j0]     + xb.x);
    atomicAdd(&g_agg[dst * 64 + c0 + 1], acc[j0 + 1] + xb.y);
}

// out[n,o] = relu(agg/max(deg,1) + x@root + bias)
template <int CIN>
__global__ void k_finalize(const float* __restrict__ Xin,
                           const float* __restrict__ root,
                           const float* __restrict__ bias,
                           float* __restrict__ out) {
    int idx = blockIdx.x * blockDim.x + threadIdx.x;
    if (idx >= N_NODES * 64) return;
    int n = idx >> 6, o = idx & 63;
    float inv = 1.f / fmaxf(g_deg[n], 1.f);
    float v = g_agg[idx] * inv + bias[o];
    const float* xr = Xin + (size_t)n * CIN;
#pragma unroll 8
    for (int i = 0; i < CIN; ++i) v = fmaf(xr[i], root[i * 64 + o], v);
    out[idx] = fmaxf(v, 0.f);
}

// readout: warp per node
__global__ void k_readout(const float* __restrict__ w1, const float* __restrict__ b1,
                          const float* __restrict__ w2, const float* __restrict__ b2,
                          float* __restrict__ out) {
    int warp = (blockIdx.x * blockDim.x + threadIdx.x) >> 5;
    int lane = threadIdx.x & 31;
    if (warp >= N_NODES) return;
    const float* zr = g_z + (size_t)warp * 64;
    float z0 = zr[lane], z1 = zr[lane + 32];
    float p[8];
#pragma unroll
    for (int j = 0; j < 8; ++j)
        p[j] = z0 * w1[lane * 8 + j] + z1 * w1[(lane + 32) * 8 + j];
    const unsigned FULL = 0xffffffffu;
#pragma unroll
    for (int off = 16; off; off >>= 1)
#pragma unroll
        for (int j = 0; j < 8; ++j) p[j] += __shfl_down_sync(FULL, p[j], off);
    if (lane == 0) {
        float r = b2[0];
#pragma unroll
        for (int j = 0; j < 8; ++j) r += fmaxf(p[j] + b1[j], 0.f) * w2[j];
        out[warp] = r;
    }
}

// ---------------------------------------------------------------------------
extern "C" void kernel_launch(void* const* d_in, const int* in_sizes, int n_in,
                              void* d_out, int out_size) {
    const float* x      = (const float*)d_in[0];
    const int*   ei     = (const int*)d_in[1];     // int32 (jax x64 disabled)
    const float* ea     = (const float*)d_in[2];
    const float* nn1_w1 = (const float*)d_in[3];
    const float* nn1_b1 = (const float*)d_in[4];
    const float* nn1_w2 = (const float*)d_in[5];
    const float* nn1_b2 = (const float*)d_in[6];
    const float* root1  = (const float*)d_in[7];
    const float* bias1  = (const float*)d_in[8];
    const float* nn2_w1 = (const float*)d_in[9];
    const float* nn2_b1 = (const float*)d_in[10];
    const float* nn2_w2 = (const float*)d_in[11];
    const float* nn2_b2 = (const float*)d_in[12];
    const float* root2  = (const float*)d_in[13];
    const float* bias2  = (const float*)d_in[14];
    const float* lin1_w = (const float*)d_in[15];
    const float* lin1_b = (const float*)d_in[16];
    const float* lin2_w = (const float*)d_in[17];
    const float* lin2_b = (const float*)d_in[18];
    float* out = (float*)d_out;

    float* d_y = nullptr; float* d_z = nullptr;
    cudaGetSymbolAddress((void**)&d_y, g_y);
    cudaGetSymbolAddress((void**)&d_z, g_z);

    const int SMEM1 = CIN1 * 64 * 2 + 8 * 16 * 72 * 4;   // 38912
    const int SMEM2 = HID  * 64 * 2 + 8 * 16 * 72 * 4;   // 45056
    cudaFuncSetAttribute(k_gemm_wmma7<CIN1>,
                         cudaFuncAttributeMaxDynamicSharedMemorySize, SMEM1);
    cudaFuncSetAttribute(k_gemm_wmma7<HID>,
                         cudaFuncAttributeMaxDynamicSharedMemorySize, SMEM2);

    const int T = 256;
    const int bNO  = (N_NODES * 64 + T - 1) / T;
    const int bE   = (N_EDGES + T - 1) / T;
    const int bEH  = (N_EDGES * 64 + T - 1) / T;
    const int bMSG = (N_EDGES * 32 + T - 1) / T;   // warp per edge
    const int bRD  = (N_NODES * 32 + T - 1) / T;
    dim3 gW(64, GY);

    // launch index 3 is profiled — keep the NEW gemm<16> there.
    k_conv_B<CIN1><<<(CIN1 * 4096 + T - 1) / T, T>>>(nn1_w2);      // 0
    k_conv_X<CIN1><<<(N_PAD * CIN1 + T - 1) / T, T>>>(x);          // 1
    k_init<<<bNO, T>>>();                                          // 2
    k_gemm_wmma7<CIN1><<<gW, 256, SMEM1>>>();                      // 3 <- profiled
    k_hist<<<bE, T>>>(ei);                                         // 4
    k_scan<<<1, 1024>>>();                                         // 5
    k_scatter<<<bE, T>>>(ei);                                      // 6
    k_edge_hidden<<<bEH, T>>>(ea, nn1_w1, nn1_b1);                 // 7
    k_xb<CIN1><<<bNO, T>>>(x, nn1_b2);                             // 8
    k_edge_msg<<<bMSG, T>>>();                                     // 9
    k_finalize<CIN1><<<bNO, T>>>(x, root1, bias1, d_y);            // 10

    // ---- layer 2 (cin = 64) ----
    k_zero_agg<<<bNO, T>>>();
    k_conv_B<HID><<<(HID * 4096 + T - 1) / T, T>>>(nn2_w2);
    k_conv_X<HID><<<(N_PAD * HID + T - 1) / T, T>>>(d_y);
    k_edge_hidden<<<bEH, T>>>(ea, nn2_w1, nn2_b1);
    k_gemm_wmma7<HID><<<gW, 256, SMEM2>>>();
    k_xb<HID><<<bNO, T>>>(d_y, nn2_b2);
    k_edge_msg<<<bMSG, T>>>();
    k_finalize<HID><<<bNO, T>>>(d_y, root2, bias2, d_z);

    // ---- readout ----
    k_readout<<<bRD, T>>>(lin1_w, lin1_b, lin2_w, lin2_b, out);
}